// round 3
// baseline (speedup 1.0000x reference)
#include <cuda_runtime.h>

#define HID      128
#define DIN      273      // 2*HID + 16 + 1
#define TE       64       // edges (or nodes) per block
#define KC       64       // K-chunk rows staged in smem
#define NTHREADS 256
#define PITCH    65       // smem pitch for [K][TE] tiles (conflict-free)
#define SIN_PAD  17748    // DIN*PITCH (=17745) rounded up to multiple of 4 -> 16B-aligned s_w
#define MAXN     50000

// Scratch for segment-summed messages (25.6 MB) — static device global (no alloc).
__device__ float g_mi[(size_t)MAXN * HID];

__device__ __forceinline__ float siluf(float v) { return v / (1.0f + __expf(-v)); }

// Block GEMM: [64 edges, K] @ [K, 128] accumulated into per-thread 2x16 register tile.
// Thread (cg = warp id 0..7, lane) owns channels [cg*16, cg*16+16) for edges lane and lane+32.
// Weights cooperatively staged in s_w in KC-row chunks; reads are warp-uniform (broadcast).
__device__ __forceinline__ void gemm_acc(const float* __restrict__ gw,
                                         const float* __restrict__ s_src,
                                         float*       __restrict__ s_w,
                                         int K, int lane, int cg,
                                         float* __restrict__ acc0,
                                         float* __restrict__ acc1)
{
    for (int kb = 0; kb < K; kb += KC) {
        int kc = (K - kb < KC) ? (K - kb) : KC;
        int nvec = kc * (HID / 4);
        const float4* gsrc = (const float4*)(gw + (size_t)kb * HID);
        float4* dv = (float4*)s_w;
        for (int i = threadIdx.x; i < nvec; i += NTHREADS) dv[i] = gsrc[i];
        __syncthreads();
        #pragma unroll 2
        for (int kk = 0; kk < kc; ++kk) {
            float a0 = s_src[(kb + kk) * PITCH + lane];
            float a1 = s_src[(kb + kk) * PITCH + lane + 32];
            const float4* wr = (const float4*)(s_w + kk * HID + cg * 16);
            #pragma unroll
            for (int q = 0; q < 4; ++q) {
                float4 w = wr[q];
                acc0[q*4+0] += a0 * w.x; acc0[q*4+1] += a0 * w.y;
                acc0[q*4+2] += a0 * w.z; acc0[q*4+3] += a0 * w.w;
                acc1[q*4+0] += a1 * w.x; acc1[q*4+1] += a1 * w.y;
                acc1[q*4+2] += a1 * w.z; acc1[q*4+3] += a1 * w.w;
            }
        }
        __syncthreads();
    }
}

__global__ __launch_bounds__(NTHREADS)
void init_kernel(const float* __restrict__ x, float* __restrict__ x_out, int N)
{
    int i = blockIdx.x * blockDim.x + threadIdx.x;
    if (i < N * HID) g_mi[i] = 0.0f;
    if (i < N * 3)   x_out[i] = x[i];
}

__global__ __launch_bounds__(NTHREADS)
void edge_kernel(const float* __restrict__ h, const float* __restrict__ x,
                 const int*   __restrict__ eidx, const float* __restrict__ eattr,
                 const float* __restrict__ em_w1, const float* __restrict__ em_b1,
                 const float* __restrict__ em_w2, const float* __restrict__ em_b2,
                 const float* __restrict__ ei_w,  const float* __restrict__ ei_b,
                 const float* __restrict__ xm_w1, const float* __restrict__ xm_b1,
                 const float* __restrict__ xm_w2,
                 float* __restrict__ x_out, int N, int E)
{
    extern __shared__ float sm[];
    float* s_in  = sm;                         // DIN*PITCH (reused as [128][PITCH] later)
    float* s_w   = s_in  + SIN_PAD;            // KC*HID (16B-aligned)
    float* s_red = s_w   + KC * HID;           // 8*64
    float* s_eij = s_red + 8 * 64;             // 64
    float* s_rxs = s_eij + 64;                 // 3*64 (rel_x * inv, premultiplied)
    int*   s_dst = (int*)(s_rxs + 3 * 64);     // 64

    int tid  = threadIdx.x;
    int lane = tid & 31;
    int cg   = tid >> 5;          // 0..7
    int e0   = lane, e1 = lane + 32;
    int ebase = blockIdx.x * TE;

    // ---- gather edge inputs into s_in[k][e]: k 0..127 = h[dst], 128..255 = h[src],
    //      256 = d_sq, 257..272 = edge_attr ----
    for (int i = 0; i < 8; ++i) {
        int e  = cg * 8 + i;
        int ge = ebase + e;
        if (ge < E) {
            int srcn = eidx[ge];
            int dstn = eidx[E + ge];
            int k0 = lane * 4;
            float4 v = ((const float4*)(h + (size_t)dstn * HID))[lane];
            s_in[(k0+0)*PITCH+e] = v.x; s_in[(k0+1)*PITCH+e] = v.y;
            s_in[(k0+2)*PITCH+e] = v.z; s_in[(k0+3)*PITCH+e] = v.w;
            float4 u = ((const float4*)(h + (size_t)srcn * HID))[lane];
            s_in[(128+k0+0)*PITCH+e] = u.x; s_in[(128+k0+1)*PITCH+e] = u.y;
            s_in[(128+k0+2)*PITCH+e] = u.z; s_in[(128+k0+3)*PITCH+e] = u.w;
            if (lane < 4) {
                float4 a = ((const float4*)(eattr + (size_t)ge * 16))[lane];
                int ka = 257 + lane * 4;
                s_in[(ka+0)*PITCH+e] = a.x; s_in[(ka+1)*PITCH+e] = a.y;
                s_in[(ka+2)*PITCH+e] = a.z; s_in[(ka+3)*PITCH+e] = a.w;
            }
            if (lane == 0) {
                float rx = x[(size_t)dstn*3+0] - x[(size_t)srcn*3+0];
                float ry = x[(size_t)dstn*3+1] - x[(size_t)srcn*3+1];
                float rz = x[(size_t)dstn*3+2] - x[(size_t)srcn*3+2];
                float dsq = rx*rx + ry*ry + rz*rz;
                s_in[256*PITCH+e] = dsq;
                float inv = 1.0f / (sqrtf(dsq + 1e-8f) + 1.0f);
                s_rxs[e]       = rx * inv;
                s_rxs[64 + e]  = ry * inv;
                s_rxs[128 + e] = rz * inv;
                s_dst[e] = dstn;
            }
        } else {
            for (int k = lane; k < DIN; k += 32) s_in[k*PITCH+e] = 0.0f;
            if (lane == 0) {
                s_dst[e] = -1;
                s_rxs[e] = s_rxs[64+e] = s_rxs[128+e] = 0.0f;
            }
        }
    }
    __syncthreads();

    float acc0[16], acc1[16];
    #pragma unroll
    for (int i = 0; i < 16; ++i) { acc0[i] = 0.0f; acc1[i] = 0.0f; }

    // ---- layer 1: edge_in @ em_w1, silu ----
    gemm_acc(em_w1, s_in, s_w, DIN, lane, cg, acc0, acc1);
    #pragma unroll
    for (int i = 0; i < 16; ++i) {
        int c = cg * 16 + i;
        float b = em_b1[c];
        s_in[c*PITCH+e0] = siluf(acc0[i] + b);
        s_in[c*PITCH+e1] = siluf(acc1[i] + b);
        acc0[i] = 0.0f; acc1[i] = 0.0f;
    }
    __syncthreads();

    // ---- layer 2: t1 @ em_w2 -> mij; edge gate partials ----
    gemm_acc(em_w2, s_in, s_w, HID, lane, cg, acc0, acc1);
    float mij0[16], mij1[16];
    float p0 = 0.0f, p1 = 0.0f;
    #pragma unroll
    for (int i = 0; i < 16; ++i) {
        int c = cg * 16 + i;
        float b = em_b2[c];
        mij0[i] = acc0[i] + b;
        mij1[i] = acc1[i] + b;
        float w = ei_w[c];
        p0 += mij0[i] * w;
        p1 += mij1[i] * w;
        acc0[i] = 0.0f; acc1[i] = 0.0f;
        s_in[c*PITCH+e0] = mij0[i];   // stash mij for the x-gate MLP
        s_in[c*PITCH+e1] = mij1[i];
    }
    s_red[cg*64+e0] = p0;
    s_red[cg*64+e1] = p1;
    __syncthreads();
    if (tid < TE) {
        float s = ei_b[0];
        #pragma unroll
        for (int g = 0; g < 8; ++g) s += s_red[g*64 + tid];
        s_eij[tid] = 1.0f / (1.0f + __expf(-s));
    }
    __syncthreads();

    // ---- scatter mi += mij * eij ----
    {
        float ej0 = s_eij[e0], ej1 = s_eij[e1];
        int d0 = s_dst[e0], d1 = s_dst[e1];
        if (d0 >= 0) {
            float* p = g_mi + (size_t)d0 * HID + cg * 16;
            #pragma unroll
            for (int i = 0; i < 16; ++i) atomicAdd(p + i, mij0[i] * ej0);
        }
        if (d1 >= 0) {
            float* p = g_mi + (size_t)d1 * HID + cg * 16;
            #pragma unroll
            for (int i = 0; i < 16; ++i) atomicAdd(p + i, mij1[i] * ej1);
        }
    }

    // ---- x-gate: silu(mij @ xm_w1 + b) @ xm_w2 -> tanh; scatter delta ----
    gemm_acc(xm_w1, s_in, s_w, HID, lane, cg, acc0, acc1);
    p0 = 0.0f; p1 = 0.0f;
    #pragma unroll
    for (int i = 0; i < 16; ++i) {
        int c = cg * 16 + i;
        float b = xm_b1[c];
        float w = xm_w2[c];
        p0 += siluf(acc0[i] + b) * w;
        p1 += siluf(acc1[i] + b) * w;
    }
    s_red[cg*64+e0] = p0;
    s_red[cg*64+e1] = p1;
    __syncthreads();
    if (tid < TE) {
        float s = 0.0f;
        #pragma unroll
        for (int g = 0; g < 8; ++g) s += s_red[g*64 + tid];
        float gate = tanhf(s);
        int d = s_dst[tid];
        if (d >= 0) {
            atomicAdd(x_out + (size_t)d*3 + 0, s_rxs[tid]       * gate);
            atomicAdd(x_out + (size_t)d*3 + 1, s_rxs[64 + tid]  * gate);
            atomicAdd(x_out + (size_t)d*3 + 2, s_rxs[128 + tid] * gate);
        }
    }
}

__global__ __launch_bounds__(NTHREADS)
void node_kernel(const float* __restrict__ h,
                 const float* __restrict__ nm_w1, const float* __restrict__ nm_b1,
                 const float* __restrict__ nm_w2, const float* __restrict__ nm_b2,
                 float* __restrict__ h_out, int N)
{
    extern __shared__ float sm[];
    float* s_in = sm;                      // 256*PITCH (16640 floats, 16B-aligned end)
    float* s_w  = sm + 256 * PITCH;        // KC*HID

    int tid  = threadIdx.x;
    int lane = tid & 31;
    int cg   = tid >> 5;
    int e0   = lane, e1 = lane + 32;
    int nbase = blockIdx.x * TE;

    // gather [mi | h] into s_in[k][e], k 0..127 = mi, 128..255 = h
    for (int i = 0; i < 8; ++i) {
        int e = cg * 8 + i;
        int n = nbase + e;
        int k0 = lane * 4;
        if (n < N) {
            float4 v = ((const float4*)(g_mi + (size_t)n * HID))[lane];
            s_in[(k0+0)*PITCH+e] = v.x; s_in[(k0+1)*PITCH+e] = v.y;
            s_in[(k0+2)*PITCH+e] = v.z; s_in[(k0+3)*PITCH+e] = v.w;
            float4 u = ((const float4*)(h + (size_t)n * HID))[lane];
            s_in[(128+k0+0)*PITCH+e] = u.x; s_in[(128+k0+1)*PITCH+e] = u.y;
            s_in[(128+k0+2)*PITCH+e] = u.z; s_in[(128+k0+3)*PITCH+e] = u.w;
        } else {
            for (int k = lane; k < 256; k += 32) s_in[k*PITCH+e] = 0.0f;
        }
    }
    __syncthreads();

    float acc0[16], acc1[16];
    #pragma unroll
    for (int i = 0; i < 16; ++i) { acc0[i] = 0.0f; acc1[i] = 0.0f; }

    gemm_acc(nm_w1, s_in, s_w, 2 * HID, lane, cg, acc0, acc1);
    #pragma unroll
    for (int i = 0; i < 16; ++i) {
        int c = cg * 16 + i;
        float b = nm_b1[c];
        s_in[c*PITCH+e0] = siluf(acc0[i] + b);
        s_in[c*PITCH+e1] = siluf(acc1[i] + b);
        acc0[i] = 0.0f; acc1[i] = 0.0f;
    }
    __syncthreads();

    gemm_acc(nm_w2, s_in, s_w, HID, lane, cg, acc0, acc1);
    int n0 = nbase + e0, n1 = nbase + e1;
    #pragma unroll
    for (int i = 0; i < 16; ++i) {
        int c = cg * 16 + i;
        float b = nm_b2[c];
        if (n0 < N) h_out[(size_t)n0*HID + c] = h[(size_t)n0*HID + c] + acc0[i] + b;
        if (n1 < N) h_out[(size_t)n1*HID + c] = h[(size_t)n1*HID + c] + acc1[i] + b;
    }
}

extern "C" void kernel_launch(void* const* d_in, const int* in_sizes, int n_in,
                              void* d_out, int out_size)
{
    const float* h     = (const float*)d_in[0];
    const float* x     = (const float*)d_in[1];
    const int*   eidx  = (const int*)  d_in[2];
    const float* eattr = (const float*)d_in[3];
    const float* em_w1 = (const float*)d_in[4];
    const float* em_b1 = (const float*)d_in[5];
    const float* em_w2 = (const float*)d_in[6];
    const float* em_b2 = (const float*)d_in[7];
    const float* ei_w  = (const float*)d_in[8];
    const float* ei_b  = (const float*)d_in[9];
    const float* xm_w1 = (const float*)d_in[10];
    const float* xm_b1 = (const float*)d_in[11];
    const float* xm_w2 = (const float*)d_in[12];
    const float* nm_w1 = (const float*)d_in[13];
    const float* nm_b1 = (const float*)d_in[14];
    const float* nm_w2 = (const float*)d_in[15];
    const float* nm_b2 = (const float*)d_in[16];

    int N = in_sizes[0] / HID;
    int E = in_sizes[3] / 16;

    float* out   = (float*)d_out;
    float* h_out = out;
    float* x_out = out + (size_t)N * HID;

    size_t smem_edge = (size_t)(SIN_PAD + KC * HID + 8 * 64 + 64 + 3 * 64 + 64) * sizeof(float);
    size_t smem_node = (size_t)(256 * PITCH + KC * HID) * sizeof(float);
    cudaFuncSetAttribute(edge_kernel, cudaFuncAttributeMaxDynamicSharedMemorySize, (int)smem_edge);
    cudaFuncSetAttribute(node_kernel, cudaFuncAttributeMaxDynamicSharedMemorySize, (int)smem_node);

    int initBlocks = (N * HID + NTHREADS - 1) / NTHREADS;
    init_kernel<<<initBlocks, NTHREADS>>>(x, x_out, N);

    int eBlocks = (E + TE - 1) / TE;
    edge_kernel<<<eBlocks, NTHREADS, smem_edge>>>(h, x, eidx, eattr,
                                                  em_w1, em_b1, em_w2, em_b2,
                                                  ei_w, ei_b, xm_w1, xm_b1, xm_w2,
                                                  x_out, N, E);

    int nBlocks = (N + TE - 1) / TE;
    node_kernel<<<nBlocks, NTHREADS, smem_node>>>(h, nm_w1, nm_b1, nm_w2, nm_b2, h_out, N);
}

// round 4
// speedup vs baseline: 1.0666x; 1.0666x over previous
#include <cuda_runtime.h>

#define HID      128
#define DIN      273      // 2*HID + 16 + 1
#define TE       64       // edges (or nodes) per block
#define KC       64       // K-chunk rows staged in smem
#define NTHREADS 256
#define PITCH    65       // smem pitch for [K][TE] tiles (conflict-free)
#define SIN_PAD  17748    // DIN*PITCH (=17745) rounded up to multiple of 4 -> 16B-aligned s_w
#define MAXN     50000

// Scratch for segment-summed messages (25.6 MB) — static device global (no alloc).
__device__ float g_mi[(size_t)MAXN * HID];

__device__ __forceinline__ float siluf(float v) { return v / (1.0f + __expf(-v)); }

typedef unsigned long long u64;

__device__ __forceinline__ u64 pack2(float x, float y) {
    u64 r;
    asm("mov.b64 %0, {%1, %2};" : "=l"(r) : "f"(x), "f"(y));
    return r;
}
__device__ __forceinline__ void unpack2(u64 v, float& lo, float& hi) {
    asm("mov.b64 {%0, %1}, %2;" : "=f"(lo), "=f"(hi) : "l"(v));
}
__device__ __forceinline__ void ffma2(u64& acc, u64 a, u64 b) {
    asm("fma.rn.f32x2 %0, %1, %2, %0;" : "+l"(acc) : "l"(a), "l"(b));
}

// Block GEMM: [64 rows, K] @ [K, 128] accumulated into per-thread packed 2x(8xf32x2) tile.
// Thread (cg = warp 0..7, lane) owns channels [cg*16, cg*16+16) for rows lane and lane+32.
// Channels packed pairwise: accP[j] holds channels (2j, 2j+1). Uses FFMA2 (fma.rn.f32x2)
// for 2 FMA lanes per fma-pipe issue. Weights staged in smem, read as LDS.128 -> 2x b64.
__device__ __forceinline__ void gemm_acc(const float* __restrict__ gw,
                                         const float* __restrict__ s_src,
                                         float*       __restrict__ s_w,
                                         int K, int lane, int cg,
                                         u64* __restrict__ acc0,
                                         u64* __restrict__ acc1)
{
    unsigned int swb = (unsigned int)__cvta_generic_to_shared(s_w) + cg * 16 * 4;
    for (int kb = 0; kb < K; kb += KC) {
        int kc = (K - kb < KC) ? (K - kb) : KC;
        int nvec = kc * (HID / 4);
        const float4* gsrc = (const float4*)(gw + (size_t)kb * HID);
        float4* dv = (float4*)s_w;
        for (int i = threadIdx.x; i < nvec; i += NTHREADS) dv[i] = gsrc[i];
        __syncthreads();
        #pragma unroll 2
        for (int kk = 0; kk < kc; ++kk) {
            float a0 = s_src[(kb + kk) * PITCH + lane];
            float a1 = s_src[(kb + kk) * PITCH + lane + 32];
            u64 a0p = pack2(a0, a0);
            u64 a1p = pack2(a1, a1);
            unsigned int base = swb + (unsigned int)(kk * HID * 4);
            #pragma unroll
            for (int q = 0; q < 4; ++q) {
                u64 w0, w1;
                asm("ld.shared.v2.b64 {%0, %1}, [%2];"
                    : "=l"(w0), "=l"(w1) : "r"(base + q * 16));
                ffma2(acc0[q*2+0], a0p, w0);
                ffma2(acc0[q*2+1], a0p, w1);
                ffma2(acc1[q*2+0], a1p, w0);
                ffma2(acc1[q*2+1], a1p, w1);
            }
        }
        __syncthreads();
    }
}

__global__ __launch_bounds__(NTHREADS)
void init_kernel(const float* __restrict__ x, float* __restrict__ x_out, int N)
{
    int i = blockIdx.x * blockDim.x + threadIdx.x;
    if (i < N * HID) g_mi[i] = 0.0f;
    if (i < N * 3)   x_out[i] = x[i];
}

__global__ __launch_bounds__(NTHREADS)
void edge_kernel(const float* __restrict__ h, const float* __restrict__ x,
                 const int*   __restrict__ eidx, const float* __restrict__ eattr,
                 const float* __restrict__ em_w1, const float* __restrict__ em_b1,
                 const float* __restrict__ em_w2, const float* __restrict__ em_b2,
                 const float* __restrict__ ei_w,  const float* __restrict__ ei_b,
                 const float* __restrict__ xm_w1, const float* __restrict__ xm_b1,
                 const float* __restrict__ xm_w2,
                 float* __restrict__ x_out, int N, int E)
{
    extern __shared__ float sm[];
    float* s_in  = sm;                         // DIN*PITCH (reused as [128][PITCH] later)
    float* s_w   = s_in  + SIN_PAD;            // KC*HID (16B-aligned)
    float* s_red = s_w   + KC * HID;           // 8*64
    float* s_eij = s_red + 8 * 64;             // 64
    float* s_rxs = s_eij + 64;                 // 3*64 (rel_x * inv, premultiplied)
    int*   s_dst = (int*)(s_rxs + 3 * 64);     // 64

    int tid  = threadIdx.x;
    int lane = tid & 31;
    int cg   = tid >> 5;          // 0..7
    int e0   = lane, e1 = lane + 32;
    int ebase = blockIdx.x * TE;

    // ---- gather edge inputs into s_in[k][e]: k 0..127 = h[dst], 128..255 = h[src],
    //      256 = d_sq, 257..272 = edge_attr ----
    for (int i = 0; i < 8; ++i) {
        int e  = cg * 8 + i;
        int ge = ebase + e;
        if (ge < E) {
            int srcn = eidx[ge];
            int dstn = eidx[E + ge];
            int k0 = lane * 4;
            float4 v = ((const float4*)(h + (size_t)dstn * HID))[lane];
            s_in[(k0+0)*PITCH+e] = v.x; s_in[(k0+1)*PITCH+e] = v.y;
            s_in[(k0+2)*PITCH+e] = v.z; s_in[(k0+3)*PITCH+e] = v.w;
            float4 u = ((const float4*)(h + (size_t)srcn * HID))[lane];
            s_in[(128+k0+0)*PITCH+e] = u.x; s_in[(128+k0+1)*PITCH+e] = u.y;
            s_in[(128+k0+2)*PITCH+e] = u.z; s_in[(128+k0+3)*PITCH+e] = u.w;
            if (lane < 4) {
                float4 a = ((const float4*)(eattr + (size_t)ge * 16))[lane];
                int ka = 257 + lane * 4;
                s_in[(ka+0)*PITCH+e] = a.x; s_in[(ka+1)*PITCH+e] = a.y;
                s_in[(ka+2)*PITCH+e] = a.z; s_in[(ka+3)*PITCH+e] = a.w;
            }
            if (lane == 0) {
                float rx = x[(size_t)dstn*3+0] - x[(size_t)srcn*3+0];
                float ry = x[(size_t)dstn*3+1] - x[(size_t)srcn*3+1];
                float rz = x[(size_t)dstn*3+2] - x[(size_t)srcn*3+2];
                float dsq = rx*rx + ry*ry + rz*rz;
                s_in[256*PITCH+e] = dsq;
                float inv = 1.0f / (sqrtf(dsq + 1e-8f) + 1.0f);
                s_rxs[e]       = rx * inv;
                s_rxs[64 + e]  = ry * inv;
                s_rxs[128 + e] = rz * inv;
                s_dst[e] = dstn;
            }
        } else {
            for (int k = lane; k < DIN; k += 32) s_in[k*PITCH+e] = 0.0f;
            if (lane == 0) {
                s_dst[e] = -1;
                s_rxs[e] = s_rxs[64+e] = s_rxs[128+e] = 0.0f;
            }
        }
    }
    __syncthreads();

    u64 acc0[8], acc1[8];
    #pragma unroll
    for (int i = 0; i < 8; ++i) { acc0[i] = 0ull; acc1[i] = 0ull; }

    // ---- layer 1: edge_in @ em_w1, silu ----
    gemm_acc(em_w1, s_in, s_w, DIN, lane, cg, acc0, acc1);
    #pragma unroll
    for (int j = 0; j < 8; ++j) {
        int c = cg * 16 + 2*j;
        float v0, v1, w0, w1;
        unpack2(acc0[j], v0, v1);
        unpack2(acc1[j], w0, w1);
        float b0 = em_b1[c], b1 = em_b1[c+1];
        s_in[(c  )*PITCH+e0] = siluf(v0 + b0);
        s_in[(c+1)*PITCH+e0] = siluf(v1 + b1);
        s_in[(c  )*PITCH+e1] = siluf(w0 + b0);
        s_in[(c+1)*PITCH+e1] = siluf(w1 + b1);
        acc0[j] = 0ull; acc1[j] = 0ull;
    }
    __syncthreads();

    // ---- layer 2: t1 @ em_w2 -> mij; edge gate partials ----
    gemm_acc(em_w2, s_in, s_w, HID, lane, cg, acc0, acc1);
    float mij0[16], mij1[16];
    float p0 = 0.0f, p1 = 0.0f;
    #pragma unroll
    for (int j = 0; j < 8; ++j) {
        int c = cg * 16 + 2*j;
        float v0, v1, w0, w1;
        unpack2(acc0[j], v0, v1);
        unpack2(acc1[j], w0, w1);
        float b0 = em_b2[c], b1 = em_b2[c+1];
        mij0[2*j]   = v0 + b0;  mij0[2*j+1] = v1 + b1;
        mij1[2*j]   = w0 + b0;  mij1[2*j+1] = w1 + b1;
        float g0 = ei_w[c], g1 = ei_w[c+1];
        p0 += mij0[2*j] * g0 + mij0[2*j+1] * g1;
        p1 += mij1[2*j] * g0 + mij1[2*j+1] * g1;
        s_in[(c  )*PITCH+e0] = mij0[2*j];
        s_in[(c+1)*PITCH+e0] = mij0[2*j+1];
        s_in[(c  )*PITCH+e1] = mij1[2*j];
        s_in[(c+1)*PITCH+e1] = mij1[2*j+1];
        acc0[j] = 0ull; acc1[j] = 0ull;
    }
    s_red[cg*64+e0] = p0;
    s_red[cg*64+e1] = p1;
    __syncthreads();
    if (tid < TE) {
        float s = ei_b[0];
        #pragma unroll
        for (int g = 0; g < 8; ++g) s += s_red[g*64 + tid];
        s_eij[tid] = 1.0f / (1.0f + __expf(-s));
    }
    __syncthreads();

    // ---- scatter mi += mij * eij ----
    {
        float ej0 = s_eij[e0], ej1 = s_eij[e1];
        int d0 = s_dst[e0], d1 = s_dst[e1];
        if (d0 >= 0) {
            float* p = g_mi + (size_t)d0 * HID + cg * 16;
            #pragma unroll
            for (int i = 0; i < 16; ++i) atomicAdd(p + i, mij0[i] * ej0);
        }
        if (d1 >= 0) {
            float* p = g_mi + (size_t)d1 * HID + cg * 16;
            #pragma unroll
            for (int i = 0; i < 16; ++i) atomicAdd(p + i, mij1[i] * ej1);
        }
    }

    // ---- x-gate: silu(mij @ xm_w1 + b) @ xm_w2 -> tanh; scatter delta ----
    gemm_acc(xm_w1, s_in, s_w, HID, lane, cg, acc0, acc1);
    p0 = 0.0f; p1 = 0.0f;
    #pragma unroll
    for (int j = 0; j < 8; ++j) {
        int c = cg * 16 + 2*j;
        float v0, v1, w0, w1;
        unpack2(acc0[j], v0, v1);
        unpack2(acc1[j], w0, w1);
        float b0 = xm_b1[c], b1 = xm_b1[c+1];
        float g0 = xm_w2[c], g1 = xm_w2[c+1];
        p0 += siluf(v0 + b0) * g0 + siluf(v1 + b1) * g1;
        p1 += siluf(w0 + b0) * g0 + siluf(w1 + b1) * g1;
    }
    s_red[cg*64+e0] = p0;
    s_red[cg*64+e1] = p1;
    __syncthreads();
    if (tid < TE) {
        float s = 0.0f;
        #pragma unroll
        for (int g = 0; g < 8; ++g) s += s_red[g*64 + tid];
        float gate = tanhf(s);
        int d = s_dst[tid];
        if (d >= 0) {
            atomicAdd(x_out + (size_t)d*3 + 0, s_rxs[tid]       * gate);
            atomicAdd(x_out + (size_t)d*3 + 1, s_rxs[64 + tid]  * gate);
            atomicAdd(x_out + (size_t)d*3 + 2, s_rxs[128 + tid] * gate);
        }
    }
}

__global__ __launch_bounds__(NTHREADS)
void node_kernel(const float* __restrict__ h,
                 const float* __restrict__ nm_w1, const float* __restrict__ nm_b1,
                 const float* __restrict__ nm_w2, const float* __restrict__ nm_b2,
                 float* __restrict__ h_out, int N)
{
    extern __shared__ float sm[];
    float* s_in = sm;                      // 256*PITCH (16640 floats, 16B-aligned end)
    float* s_w  = sm + 256 * PITCH;        // KC*HID

    int tid  = threadIdx.x;
    int lane = tid & 31;
    int cg   = tid >> 5;
    int e0   = lane, e1 = lane + 32;
    int nbase = blockIdx.x * TE;

    // gather [mi | h] into s_in[k][e], k 0..127 = mi, 128..255 = h
    for (int i = 0; i < 8; ++i) {
        int e = cg * 8 + i;
        int n = nbase + e;
        int k0 = lane * 4;
        if (n < N) {
            float4 v = ((const float4*)(g_mi + (size_t)n * HID))[lane];
            s_in[(k0+0)*PITCH+e] = v.x; s_in[(k0+1)*PITCH+e] = v.y;
            s_in[(k0+2)*PITCH+e] = v.z; s_in[(k0+3)*PITCH+e] = v.w;
            float4 u = ((const float4*)(h + (size_t)n * HID))[lane];
            s_in[(128+k0+0)*PITCH+e] = u.x; s_in[(128+k0+1)*PITCH+e] = u.y;
            s_in[(128+k0+2)*PITCH+e] = u.z; s_in[(128+k0+3)*PITCH+e] = u.w;
        } else {
            for (int k = lane; k < 256; k += 32) s_in[k*PITCH+e] = 0.0f;
        }
    }
    __syncthreads();

    u64 acc0[8], acc1[8];
    #pragma unroll
    for (int i = 0; i < 8; ++i) { acc0[i] = 0ull; acc1[i] = 0ull; }

    gemm_acc(nm_w1, s_in, s_w, 2 * HID, lane, cg, acc0, acc1);
    #pragma unroll
    for (int j = 0; j < 8; ++j) {
        int c = cg * 16 + 2*j;
        float v0, v1, w0, w1;
        unpack2(acc0[j], v0, v1);
        unpack2(acc1[j], w0, w1);
        float b0 = nm_b1[c], b1 = nm_b1[c+1];
        s_in[(c  )*PITCH+e0] = siluf(v0 + b0);
        s_in[(c+1)*PITCH+e0] = siluf(v1 + b1);
        s_in[(c  )*PITCH+e1] = siluf(w0 + b0);
        s_in[(c+1)*PITCH+e1] = siluf(w1 + b1);
        acc0[j] = 0ull; acc1[j] = 0ull;
    }
    __syncthreads();

    gemm_acc(nm_w2, s_in, s_w, HID, lane, cg, acc0, acc1);
    int n0 = nbase + e0, n1 = nbase + e1;
    #pragma unroll
    for (int j = 0; j < 8; ++j) {
        int c = cg * 16 + 2*j;
        float v0, v1, w0, w1;
        unpack2(acc0[j], v0, v1);
        unpack2(acc1[j], w0, w1);
        float b0 = nm_b2[c], b1 = nm_b2[c+1];
        if (n0 < N) {
            h_out[(size_t)n0*HID + c]     = h[(size_t)n0*HID + c]     + v0 + b0;
            h_out[(size_t)n0*HID + c + 1] = h[(size_t)n0*HID + c + 1] + v1 + b1;
        }
        if (n1 < N) {
            h_out[(size_t)n1*HID + c]     = h[(size_t)n1*HID + c]     + w0 + b0;
            h_out[(size_t)n1*HID + c + 1] = h[(size_t)n1*HID + c + 1] + w1 + b1;
        }
    }
}

extern "C" void kernel_launch(void* const* d_in, const int* in_sizes, int n_in,
                              void* d_out, int out_size)
{
    const float* h     = (const float*)d_in[0];
    const float* x     = (const float*)d_in[1];
    const int*   eidx  = (const int*)  d_in[2];
    const float* eattr = (const float*)d_in[3];
    const float* em_w1 = (const float*)d_in[4];
    const float* em_b1 = (const float*)d_in[5];
    const float* em_w2 = (const float*)d_in[6];
    const float* em_b2 = (const float*)d_in[7];
    const float* ei_w  = (const float*)d_in[8];
    const float* ei_b  = (const float*)d_in[9];
    const float* xm_w1 = (const float*)d_in[10];
    const float* xm_b1 = (const float*)d_in[11];
    const float* xm_w2 = (const float*)d_in[12];
    const float* nm_w1 = (const float*)d_in[13];
    const float* nm_b1 = (const float*)d_in[14];
    const float* nm_w2 = (const float*)d_in[15];
    const float* nm_b2 = (const float*)d_in[16];

    int N = in_sizes[0] / HID;
    int E = in_sizes[3] / 16;

    float* out   = (float*)d_out;
    float* h_out = out;
    float* x_out = out + (size_t)N * HID;

    size_t smem_edge = (size_t)(SIN_PAD + KC * HID + 8 * 64 + 64 + 3 * 64 + 64) * sizeof(float);
    size_t smem_node = (size_t)(256 * PITCH + KC * HID) * sizeof(float);
    cudaFuncSetAttribute(edge_kernel, cudaFuncAttributeMaxDynamicSharedMemorySize, (int)smem_edge);
    cudaFuncSetAttribute(node_kernel, cudaFuncAttributeMaxDynamicSharedMemorySize, (int)smem_node);

    int initBlocks = (N * HID + NTHREADS - 1) / NTHREADS;
    init_kernel<<<initBlocks, NTHREADS>>>(x, x_out, N);

    int eBlocks = (E + TE - 1) / TE;
    edge_kernel<<<eBlocks, NTHREADS, smem_edge>>>(h, x, eidx, eattr,
                                                  em_w1, em_b1, em_w2, em_b2,
                                                  ei_w, ei_b, xm_w1, xm_b1, xm_w2,
                                                  x_out, N, E);

    int nBlocks = (N + TE - 1) / TE;
    node_kernel<<<nBlocks, NTHREADS, smem_node>>>(h, nm_w1, nm_b1, nm_w2, nm_b2, h_out, N);
}